// round 6
// baseline (speedup 1.0000x reference)
#include <cuda_runtime.h>
#include <math_constants.h>

#define BB 32
#define CC 1024
#define HW 784
#define NF4 196          // HW/4
#define REDU 64
#define TD 768
#define AD 256
#define NCH 32           // c-chunks for scores pass (32 channels each)

// ---- scratch (device globals; no allocation allowed) ----
__device__ float d_avg[BB*CC];
__device__ float d_maxv[BB*CC];
__device__ float d_chattn[BB*CC];
__device__ float d_g[BB*CC];      // qk*chattn/16
__device__ float d_h[BB*CC];      // u*chattn
__device__ float d_q[BB*AD];
__device__ float d_u[CC];
__device__ float d_pS[BB*NCH*HW]; // score partials
__device__ float d_pY[BB*NCH*HW]; // y partials
__device__ float d_s[BB];

__device__ __forceinline__ float warp_sum(float v){
  #pragma unroll
  for (int o=16;o;o>>=1) v += __shfl_xor_sync(0xffffffffu, v, o);
  return v;
}
__device__ __forceinline__ float warp_max(float v){
  #pragma unroll
  for (int o=16;o;o>>=1) v = fmaxf(v, __shfl_xor_sync(0xffffffffu, v, o));
  return v;
}

// ---------------------------------------------------------------------------
// Kernel A: fused front. blocks [0,4096): mean/max sweep (warp per row).
//           blocks [4096,4100): u = wo@wv.  blocks [4100,4356): q = tf@wq^T.
// ---------------------------------------------------------------------------
__global__ void kA(const float* __restrict__ x,
                   const float* __restrict__ wv, const float* __restrict__ wo,
                   const float* __restrict__ tf, const float* __restrict__ wq){
  __shared__ float sh[TD];
  int bid = blockIdx.x, tid = threadIdx.x;
  if (bid < 4096){
    int warp = tid>>5, lane = tid&31;
    int row = bid*8 + warp;
    const float4* xr = (const float4*)(x + (size_t)row*HW);
    // fully batched loads: 6 unconditional + 1 predicated (196 float4 per row)
    float4 v0 = xr[lane      ];
    float4 v1 = xr[lane +  32];
    float4 v2 = xr[lane +  64];
    float4 v3 = xr[lane +  96];
    float4 v4 = xr[lane + 128];
    float4 v5 = xr[lane + 160];
    bool t = lane < 4;
    float4 v6 = t ? xr[lane + 192] : make_float4(0.f,0.f,0.f,0.f);
    float s = ((v0.x+v0.y)+(v0.z+v0.w)) + ((v1.x+v1.y)+(v1.z+v1.w))
            + ((v2.x+v2.y)+(v2.z+v2.w)) + ((v3.x+v3.y)+(v3.z+v3.w))
            + ((v4.x+v4.y)+(v4.z+v4.w)) + ((v5.x+v5.y)+(v5.z+v5.w))
            + ((v6.x+v6.y)+(v6.z+v6.w));
    float m = fmaxf(fmaxf(fmaxf(v0.x,v0.y),fmaxf(v0.z,v0.w)),
              fmaxf(fmaxf(fmaxf(v1.x,v1.y),fmaxf(v1.z,v1.w)),
              fmaxf(fmaxf(fmaxf(v2.x,v2.y),fmaxf(v2.z,v2.w)),
              fmaxf(fmaxf(fmaxf(v3.x,v3.y),fmaxf(v3.z,v3.w)),
              fmaxf(fmaxf(fmaxf(v4.x,v4.y),fmaxf(v4.z,v4.w)),
                    fmaxf(fmaxf(v5.x,v5.y),fmaxf(v5.z,v5.w)))))));
    if (t) m = fmaxf(m, fmaxf(fmaxf(v6.x,v6.y),fmaxf(v6.z,v6.w)));
    s = warp_sum(s); m = warp_max(m);
    if ((tid&31)==0){ d_avg[row] = s*(1.f/(float)HW); d_maxv[row] = m; }
  } else if (bid < 4100){
    // u[c] = sum_a wo[a]*wv[a,c]
    if (tid < AD) sh[tid] = wo[tid];
    __syncthreads();
    int c = (bid-4096)*256 + tid;
    float acc = 0.f;
    #pragma unroll 8
    for (int a=0;a<AD;a++) acc += sh[a]*wv[a*CC + c];
    d_u[c] = acc;
  } else {
    // q[b,a] = dot(tf[b,:], wq[a,:]); 256 blocks = (8 achunk x 32 b)
    int qb = bid - 4100;
    int chunk = qb & 7, b = qb >> 3;
    int warp = tid>>5, lane = tid&31;
    for (int i=tid;i<TD;i+=256) sh[i] = tf[b*TD+i];
    __syncthreads();
    int a0 = chunk*32 + warp*4;
    const float* w0 = wq + (a0+0)*TD;
    const float* w1 = wq + (a0+1)*TD;
    const float* w2 = wq + (a0+2)*TD;
    const float* w3 = wq + (a0+3)*TD;
    float acc0=0.f,acc1=0.f,acc2=0.f,acc3=0.f;
    #pragma unroll 4
    for (int i=lane;i<TD;i+=32){
      float tt = sh[i];
      acc0 += w0[i]*tt; acc1 += w1[i]*tt; acc2 += w2[i]*tt; acc3 += w3[i]*tt;
    }
    acc0=warp_sum(acc0); acc1=warp_sum(acc1); acc2=warp_sum(acc2); acc3=warp_sum(acc3);
    if (lane==0){
      d_q[b*AD+a0+0]=acc0; d_q[b*AD+a0+1]=acc1;
      d_q[b*AD+a0+2]=acc2; d_q[b*AD+a0+3]=acc3;
    }
  }
}

// ---------------------------------------------------------------------------
// Kernel B: per-b (512 thr): hidden MLP -> ch_attn; qk = q@wk inline -> g, h.
// ---------------------------------------------------------------------------
__global__ void kB(const float* __restrict__ w1, const float* __restrict__ w2,
                   const float* __restrict__ wk){
  int b = blockIdx.x, tid = threadIdx.x, warp = tid>>5, lane = tid&31;
  __shared__ float s_avg[CC], s_max[CC], s_hs[REDU], s_q[AD];
  #pragma unroll
  for (int j=0;j<2;j++){ int c=tid+512*j; s_avg[c]=d_avg[b*CC+c]; s_max[c]=d_maxv[b*CC+c]; }
  if (tid < AD) s_q[tid] = d_q[b*AD+tid];
  __syncthreads();
  // 16 warps x 4 rows, 2 rows at a time with ILP
  #pragma unroll
  for (int rr=0; rr<2; rr++){
    int r0 = warp*4 + rr*2;
    const float* wr0 = w1 + (size_t)r0*CC;
    const float* wr1 = wr0 + CC;
    float a0=0.f,m0=0.f,a1=0.f,m1=0.f;
    #pragma unroll 4
    for (int i=lane;i<CC;i+=32){
      float va=s_avg[i], vm=s_max[i];
      float u0=wr0[i], u1=wr1[i];
      a0+=u0*va; m0+=u0*vm; a1+=u1*va; m1+=u1*vm;
    }
    a0=warp_sum(a0); m0=warp_sum(m0); a1=warp_sum(a1); m1=warp_sum(m1);
    if (lane==0){
      s_hs[r0  ] = fmaxf(a0,0.f)+fmaxf(m0,0.f);
      s_hs[r0+1] = fmaxf(a1,0.f)+fmaxf(m1,0.f);
    }
  }
  __syncthreads();
  #pragma unroll
  for (int j=0;j<2;j++){
    int c = tid + 512*j;
    const float4* w2v = (const float4*)(w2 + (size_t)c*REDU);
    float acc = 0.f;
    #pragma unroll
    for (int r4=0;r4<REDU/4;r4++){
      float4 wv4 = w2v[r4];
      acc += wv4.x*s_hs[r4*4+0] + wv4.y*s_hs[r4*4+1]
           + wv4.z*s_hs[r4*4+2] + wv4.w*s_hs[r4*4+3];
    }
    float ch = 1.f/(1.f+__expf(-acc));
    float qk = 0.f;
    #pragma unroll 8
    for (int a=0;a<AD;a++) qk += s_q[a]*wk[a*CC + c];
    d_chattn[b*CC+c] = ch;
    d_g[b*CC+c] = qk * ch * 0.0625f;   // /sqrt(256)
    d_h[b*CC+c] = d_u[c] * ch;
  }
}

// ---------------------------------------------------------------------------
// Kernel C: dual channel-contraction, float4. grid (32, 32), 224 thr.
// ---------------------------------------------------------------------------
__global__ void kC(const float* __restrict__ x){
  int chunk = blockIdx.x, b = blockIdx.y, tid = threadIdx.x;
  __shared__ float sg[32], shh[32];
  if (tid<32){
    sg[tid]  = d_g[b*CC + chunk*32 + tid];
    shh[tid] = d_h[b*CC + chunk*32 + tid];
  }
  __syncthreads();
  if (tid >= NF4) return;
  const float4* xb4 = (const float4*)(x + ((size_t)b*CC + chunk*32)*HW);
  float4 aS = make_float4(0.f,0.f,0.f,0.f);
  float4 aY = make_float4(0.f,0.f,0.f,0.f);
  #pragma unroll 8
  for (int c=0;c<32;c++){
    float4 v = xb4[c*NF4 + tid];
    float gc = sg[c], hc = shh[c];
    aS.x += gc*v.x; aS.y += gc*v.y; aS.z += gc*v.z; aS.w += gc*v.w;
    aY.x += hc*v.x; aY.y += hc*v.y; aY.z += hc*v.z; aY.w += hc*v.w;
  }
  ((float4*)(d_pS + ((size_t)b*NCH + chunk)*HW))[tid] = aS;
  ((float4*)(d_pY + ((size_t)b*NCH + chunk)*HW))[tid] = aY;
}

// ---------------------------------------------------------------------------
// Kernel D: reduce partials, softmax, s[b]=sigmoid(sum e*y/sum e), out2.
// ---------------------------------------------------------------------------
__global__ void kD(float* __restrict__ out2){
  int b=blockIdx.x, tid=threadIdx.x, warp=tid>>5, lane=tid&31;
  __shared__ float redA[32], redB[32], bcast[1];
  __shared__ float s_sv;
  bool act = tid < HW;
  float sc = 0.f, y = 0.f;
  if (act){
    #pragma unroll 8
    for (int k=0;k<NCH;k++){
      size_t off = ((size_t)b*NCH+k)*HW + tid;
      sc += d_pS[off];
      y  += d_pY[off];
    }
  }
  float m = act ? sc : -CUDART_INF_F;
  m = warp_max(m);
  if (lane==0) redA[warp]=m;
  __syncthreads();
  if (tid==0){ float mm=redA[0]; for(int i=1;i<25;i++) mm=fmaxf(mm,redA[i]); bcast[0]=mm; }
  __syncthreads();
  float mm = bcast[0];
  float e = act ? __expf(sc-mm) : 0.f;
  float se  = warp_sum(e);
  float sey = warp_sum(e*y);
  __syncthreads();
  if (lane==0){ redA[warp]=se; redB[warp]=sey; }
  __syncthreads();
  if (tid==0){
    float te=0.f, tey=0.f;
    for(int i=0;i<25;i++){ te+=redA[i]; tey+=redB[i]; }
    float sv = 1.f/(1.f+__expf(-tey/te));
    d_s[b]=sv; s_sv=sv;
  }
  __syncthreads();
  if (out2 && act) out2[b*HW+tid] = s_sv;
}

// ---------------------------------------------------------------------------
// Kernel E: out[b,c,:] = x[b,c,:] * ch_attn[b,c] * s[b]. Warp per row.
// ---------------------------------------------------------------------------
__global__ void kE(const float* __restrict__ x, float* __restrict__ out){
  int warp=threadIdx.x>>5, lane=threadIdx.x&31;
  int row=blockIdx.x*8+warp;
  float scale = d_chattn[row]*d_s[row>>10];
  const float4* xr=(const float4*)(x+(size_t)row*HW);
  float4* orow=(float4*)(out+(size_t)row*HW);
  float4 v0 = xr[lane      ];
  float4 v1 = xr[lane +  32];
  float4 v2 = xr[lane +  64];
  float4 v3 = xr[lane +  96];
  float4 v4 = xr[lane + 128];
  float4 v5 = xr[lane + 160];
  bool t = lane < 4;
  float4 v6 = t ? xr[lane + 192] : make_float4(0.f,0.f,0.f,0.f);
  v0.x*=scale; v0.y*=scale; v0.z*=scale; v0.w*=scale;
  v1.x*=scale; v1.y*=scale; v1.z*=scale; v1.w*=scale;
  v2.x*=scale; v2.y*=scale; v2.z*=scale; v2.w*=scale;
  v3.x*=scale; v3.y*=scale; v3.z*=scale; v3.w*=scale;
  v4.x*=scale; v4.y*=scale; v4.z*=scale; v4.w*=scale;
  v5.x*=scale; v5.y*=scale; v5.z*=scale; v5.w*=scale;
  v6.x*=scale; v6.y*=scale; v6.z*=scale; v6.w*=scale;
  orow[lane      ] = v0;
  orow[lane +  32] = v1;
  orow[lane +  64] = v2;
  orow[lane +  96] = v3;
  orow[lane + 128] = v4;
  orow[lane + 160] = v5;
  if (t) orow[lane + 192] = v6;
}

extern "C" void kernel_launch(void* const* d_in, const int* in_sizes, int n_in,
                              void* d_out, int out_size){
  const float* x  = (const float*)d_in[0];
  const float* tf = (const float*)d_in[1];
  const float* w1 = (const float*)d_in[2];
  const float* w2 = (const float*)d_in[3];
  const float* wq = (const float*)d_in[4];
  const float* wk = (const float*)d_in[5];
  const float* wv = (const float*)d_in[6];
  const float* wo = (const float*)d_in[7];
  float* out = (float*)d_out;
  long long main_elems = (long long)BB*CC*HW;
  float* out2 = ((long long)out_size >= main_elems + (long long)BB*HW)
                  ? out + main_elems : nullptr;

  kA<<<4356, 256>>>(x, wv, wo, tf, wq);
  kB<<<BB, 512>>>(w1, w2, wk);
  kC<<<dim3(NCH, BB), 224>>>(x);
  kD<<<BB, 800>>>(out2);
  kE<<<4096, 256>>>(x, out);
}

// round 7
// speedup vs baseline: 1.3429x; 1.3429x over previous
#include <cuda_runtime.h>
#include <math_constants.h>

#define BB 32
#define CC 1024
#define HW 784
#define NF4 196          // HW/4
#define REDU 64
#define TD 768
#define AD 256
#define NCH 8            // c-chunks for scores pass (128 channels each)

// ---- scratch (device globals; no allocation allowed) ----
__device__ float d_avg[BB*CC];
__device__ float d_maxv[BB*CC];
__device__ float d_chattn[BB*CC];
__device__ float d_g[BB*CC];      // qk*chattn/16
__device__ float d_h[BB*CC];      // u*chattn
__device__ float d_qk[BB*CC];
__device__ float d_q[BB*AD];
__device__ float d_u[CC];
__device__ float d_pS[BB*NCH*HW]; // score partials
__device__ float d_pY[BB*NCH*HW]; // y partials
__device__ float d_s[BB];

__device__ __forceinline__ float warp_sum(float v){
  #pragma unroll
  for (int o=16;o;o>>=1) v += __shfl_xor_sync(0xffffffffu, v, o);
  return v;
}
__device__ __forceinline__ float warp_max(float v){
  #pragma unroll
  for (int o=16;o;o>>=1) v = fmaxf(v, __shfl_xor_sync(0xffffffffu, v, o));
  return v;
}

// ---------------------------------------------------------------------------
// kU: u[c] = sum_a wo[a]*wv[a,c]   (side stream, weights only)
// ---------------------------------------------------------------------------
__global__ void kU(const float* __restrict__ wv, const float* __restrict__ wo){
  __shared__ float s_wo[AD];
  int tid = threadIdx.x;
  if (tid < AD) s_wo[tid] = wo[tid];
  __syncthreads();
  int c = blockIdx.x*256 + tid;
  float acc = 0.f;
  #pragma unroll 8
  for (int a=0;a<AD;a++) acc += s_wo[a]*wv[a*CC + c];
  d_u[c] = acc;
}

// ---------------------------------------------------------------------------
// kQ: q[b,a] = dot(tf[b,:], wq[a,:]).  grid (8, 32), 256 thr. (side stream)
// ---------------------------------------------------------------------------
__global__ void kQ(const float* __restrict__ tf, const float* __restrict__ wq){
  int chunk = blockIdx.x, b = blockIdx.y;
  int tid = threadIdx.x, warp = tid>>5, lane = tid&31;
  __shared__ float s_tf[TD];
  for (int i=tid;i<TD;i+=256) s_tf[i] = tf[b*TD+i];
  __syncthreads();
  int a0 = chunk*32 + warp*4;
  const float* w0 = wq + (a0+0)*TD;
  const float* w1 = wq + (a0+1)*TD;
  const float* w2 = wq + (a0+2)*TD;
  const float* w3 = wq + (a0+3)*TD;
  float acc0=0.f,acc1=0.f,acc2=0.f,acc3=0.f;
  #pragma unroll 4
  for (int i=lane;i<TD;i+=32){
    float t = s_tf[i];
    acc0 += w0[i]*t; acc1 += w1[i]*t; acc2 += w2[i]*t; acc3 += w3[i]*t;
  }
  acc0=warp_sum(acc0); acc1=warp_sum(acc1); acc2=warp_sum(acc2); acc3=warp_sum(acc3);
  if (lane==0){
    d_q[b*AD+a0+0]=acc0; d_q[b*AD+a0+1]=acc1;
    d_q[b*AD+a0+2]=acc2; d_q[b*AD+a0+3]=acc3;
  }
}

// ---------------------------------------------------------------------------
// kQK: qk[b,c] = sum_a q[b,a]*wk[a,c].  grid (4, 32), 256 thr. (side stream)
// ---------------------------------------------------------------------------
__global__ void kQK(const float* __restrict__ wk){
  int cchunk = blockIdx.x, b = blockIdx.y, tid = threadIdx.x;
  __shared__ float s_q[AD];
  if (tid < AD) s_q[tid] = d_q[b*AD+tid];
  __syncthreads();
  int c = cchunk*256 + tid;
  float qk = 0.f;
  #pragma unroll 8
  for (int a=0;a<AD;a++) qk += s_q[a]*wk[a*CC + c];
  d_qk[b*CC+c] = qk;
}

// ---------------------------------------------------------------------------
// K1: per (b,c) row: mean + max over 784. Warp per row. grid 4096 x 256.
// ---------------------------------------------------------------------------
__global__ void k1_reduce(const float* __restrict__ x){
  int warp = threadIdx.x>>5, lane = threadIdx.x&31;
  int row = blockIdx.x*8 + warp;
  const float4* xr = (const float4*)(x + (size_t)row*HW);
  float s = 0.f, m = -CUDART_INF_F;
  #pragma unroll 2
  for (int i=lane; i<NF4; i+=32){
    float4 v = xr[i];
    s += (v.x+v.y)+(v.z+v.w);
    m = fmaxf(m, fmaxf(fmaxf(v.x,v.y), fmaxf(v.z,v.w)));
  }
  s = warp_sum(s); m = warp_max(m);
  if (lane==0){ d_avg[row] = s*(1.f/(float)HW); d_maxv[row] = m; }
}

// ---------------------------------------------------------------------------
// K2 fused: per-b block (512 thr): hidden MLP -> ch_attn -> g, h (uses d_qk).
// ---------------------------------------------------------------------------
__global__ void k2_fused(const float* __restrict__ w1, const float* __restrict__ w2){
  int b = blockIdx.x, tid = threadIdx.x, warp = tid>>5, lane = tid&31;
  __shared__ float s_avg[CC], s_max[CC], s_hs[REDU];
  #pragma unroll
  for (int j=0;j<2;j++){ int c=tid+512*j; s_avg[c]=d_avg[b*CC+c]; s_max[c]=d_maxv[b*CC+c]; }
  __syncthreads();
  // 16 warps x 4 rows, 2 rows at a time with ILP
  #pragma unroll
  for (int rr=0; rr<2; rr++){
    int r0 = warp*4 + rr*2;
    const float* wr0 = w1 + (size_t)r0*CC;
    const float* wr1 = wr0 + CC;
    float a0=0.f,m0=0.f,a1=0.f,m1=0.f;
    #pragma unroll 4
    for (int i=lane;i<CC;i+=32){
      float va=s_avg[i], vm=s_max[i];
      float u0=wr0[i], u1=wr1[i];
      a0+=u0*va; m0+=u0*vm; a1+=u1*va; m1+=u1*vm;
    }
    a0=warp_sum(a0); m0=warp_sum(m0); a1=warp_sum(a1); m1=warp_sum(m1);
    if (lane==0){
      s_hs[r0  ] = fmaxf(a0,0.f)+fmaxf(m0,0.f);
      s_hs[r0+1] = fmaxf(a1,0.f)+fmaxf(m1,0.f);
    }
  }
  __syncthreads();
  #pragma unroll
  for (int j=0;j<2;j++){
    int c = tid + 512*j;
    const float4* w2v = (const float4*)(w2 + (size_t)c*REDU);
    float acc = 0.f;
    #pragma unroll
    for (int r4=0;r4<REDU/4;r4++){
      float4 wv4 = w2v[r4];
      acc += wv4.x*s_hs[r4*4+0] + wv4.y*s_hs[r4*4+1]
           + wv4.z*s_hs[r4*4+2] + wv4.w*s_hs[r4*4+3];
    }
    float ch = 1.f/(1.f+__expf(-acc));
    d_chattn[b*CC+c] = ch;
    d_g[b*CC+c] = d_qk[b*CC+c] * ch * 0.0625f;   // /sqrt(256)
    d_h[b*CC+c] = d_u[c] * ch;
  }
}

// ---------------------------------------------------------------------------
// K3: dual channel-contraction, float4. grid (NCH, 32), 224 thr (196 active).
// Each chunk covers 128 channels.
// ---------------------------------------------------------------------------
__global__ void k3_scores(const float* __restrict__ x){
  int chunk = blockIdx.x, b = blockIdx.y, tid = threadIdx.x;
  __shared__ float sg[128], shh[128];
  if (tid<128){
    sg[tid]  = d_g[b*CC + chunk*128 + tid];
    shh[tid] = d_h[b*CC + chunk*128 + tid];
  }
  __syncthreads();
  if (tid >= NF4) return;
  const float4* xb4 = (const float4*)(x + ((size_t)b*CC + chunk*128)*HW);
  float4 aS = make_float4(0.f,0.f,0.f,0.f);
  float4 aY = make_float4(0.f,0.f,0.f,0.f);
  #pragma unroll 8
  for (int c=0;c<128;c++){
    float4 v = xb4[c*NF4 + tid];
    float gc = sg[c], hc = shh[c];
    aS.x += gc*v.x; aS.y += gc*v.y; aS.z += gc*v.z; aS.w += gc*v.w;
    aY.x += hc*v.x; aY.y += hc*v.y; aY.z += hc*v.z; aY.w += hc*v.w;
  }
  ((float4*)(d_pS + ((size_t)b*NCH + chunk)*HW))[tid] = aS;
  ((float4*)(d_pY + ((size_t)b*NCH + chunk)*HW))[tid] = aY;
}

// ---------------------------------------------------------------------------
// K4: reduce partials, softmax, s[b]=sigmoid(sum e*y / sum e), write out2.
// grid 32, 800 thr (784 active).
// ---------------------------------------------------------------------------
__global__ void k4_final(float* __restrict__ out2){
  int b=blockIdx.x, tid=threadIdx.x, warp=tid>>5, lane=tid&31;
  __shared__ float redA[32], redB[32], bcast[1];
  __shared__ float s_sv;
  bool act = tid < HW;
  float sc = 0.f, y = 0.f;
  if (act){
    #pragma unroll
    for (int k=0;k<NCH;k++){
      size_t off = ((size_t)b*NCH+k)*HW + tid;
      sc += d_pS[off];
      y  += d_pY[off];
    }
  }
  float m = act ? sc : -CUDART_INF_F;
  m = warp_max(m);
  if (lane==0) redA[warp]=m;
  __syncthreads();
  if (tid==0){ float mm=redA[0]; for(int i=1;i<25;i++) mm=fmaxf(mm,redA[i]); bcast[0]=mm; }
  __syncthreads();
  float mm = bcast[0];
  float e = act ? __expf(sc-mm) : 0.f;
  float se  = warp_sum(e);
  float sey = warp_sum(e*y);
  __syncthreads();
  if (lane==0){ redA[warp]=se; redB[warp]=sey; }
  __syncthreads();
  if (tid==0){
    float te=0.f, tey=0.f;
    for(int i=0;i<25;i++){ te+=redA[i]; tey+=redB[i]; }
    float sv = 1.f/(1.f+__expf(-tey/te));
    d_s[b]=sv; s_sv=sv;
  }
  __syncthreads();
  if (out2 && act) out2[b*HW+tid] = s_sv;
}

// ---------------------------------------------------------------------------
// K7: out[b,c,:] = x[b,c,:] * ch_attn[b,c] * s[b]. Warp per row, float4.
// ---------------------------------------------------------------------------
__global__ void k7_out(const float* __restrict__ x, float* __restrict__ out){
  int warp=threadIdx.x>>5, lane=threadIdx.x&31;
  int row=blockIdx.x*8+warp;
  float scale = d_chattn[row]*d_s[row>>10];
  const float4* xr=(const float4*)(x+(size_t)row*HW);
  float4* orow=(float4*)(out+(size_t)row*HW);
  #pragma unroll 2
  for (int i=lane;i<NF4;i+=32){
    float4 v=xr[i];
    v.x*=scale; v.y*=scale; v.z*=scale; v.w*=scale;
    orow[i]=v;
  }
}

// ---- side stream + fork/join events (static-init; mem-checkpoint delta 0) --
struct SideStream {
  cudaStream_t s; cudaEvent_t fork, join;
  SideStream(){
    cudaStreamCreateWithFlags(&s, cudaStreamNonBlocking);
    cudaEventCreateWithFlags(&fork, cudaEventDisableTiming);
    cudaEventCreateWithFlags(&join, cudaEventDisableTiming);
  }
};
static SideStream g_ss;

extern "C" void kernel_launch(void* const* d_in, const int* in_sizes, int n_in,
                              void* d_out, int out_size){
  const float* x  = (const float*)d_in[0];
  const float* tf = (const float*)d_in[1];
  const float* w1 = (const float*)d_in[2];
  const float* w2 = (const float*)d_in[3];
  const float* wq = (const float*)d_in[4];
  const float* wk = (const float*)d_in[5];
  const float* wv = (const float*)d_in[6];
  const float* wo = (const float*)d_in[7];
  float* out = (float*)d_out;
  long long main_elems = (long long)BB*CC*HW;
  float* out2 = ((long long)out_size >= main_elems + (long long)BB*HW)
                  ? out + main_elems : nullptr;

  // fork side chain (text/weights only) to overlap with k1's DRAM sweep
  cudaEventRecord(g_ss.fork, 0);
  cudaStreamWaitEvent(g_ss.s, g_ss.fork, 0);
  kU <<<4, 256, 0, g_ss.s>>>(wv, wo);
  kQ <<<dim3(8, BB), 256, 0, g_ss.s>>>(tf, wq);
  kQK<<<dim3(4, BB), 256, 0, g_ss.s>>>(wk);
  cudaEventRecord(g_ss.join, g_ss.s);

  k1_reduce <<<4096, 256>>>(x);
  cudaStreamWaitEvent(0, g_ss.join, 0);
  k2_fused  <<<BB, 512>>>(w1, w2);
  k3_scores <<<dim3(NCH, BB), 224>>>(x);
  k4_final  <<<BB, 800>>>(out2);
  k7_out    <<<4096, 256>>>(x, out);
}

// round 8
// speedup vs baseline: 1.5451x; 1.1506x over previous
#include <cuda_runtime.h>
#include <math_constants.h>

#define BB 32
#define CC 1024
#define HW 784
#define NF4 196          // HW/4
#define REDU 64
#define TD 768
#define AD 256
#define NCH 16           // chunks for contraction: 64 channels each
#define NCHC 64          // CC/NCH
#define NB 592           // 4 blocks/SM * 148 SMs (residency-safe)

// ---- scratch (device globals; zero-initialized; no allocation allowed) ----
__device__ float d_avg[BB*CC];
__device__ float d_maxv[BB*CC];
__device__ float d_chattn[BB*CC];
__device__ float d_g[BB*CC];
__device__ float d_h[BB*CC];
__device__ float d_qk[BB*CC];
__device__ float d_hs[BB*REDU];
__device__ float d_q[BB*AD];
__device__ float d_u[CC];
__device__ float d_pS[BB*NCH*HW];
__device__ float d_pY[BB*NCH*HW];
__device__ float d_s[BB];
__device__ unsigned int g_count;
__device__ volatile unsigned int g_gen;

__device__ __forceinline__ float warp_sum(float v){
  #pragma unroll
  for (int o=16;o;o>>=1) v += __shfl_xor_sync(0xffffffffu, v, o);
  return v;
}
__device__ __forceinline__ float warp_max(float v){
  #pragma unroll
  for (int o=16;o;o>>=1) v = fmaxf(v, __shfl_xor_sync(0xffffffffu, v, o));
  return v;
}

// software grid barrier: all NB blocks resident by construction.
__device__ __forceinline__ void gbar(){
  __threadfence();           // each thread publishes its own prior stores
  __syncthreads();
  if (threadIdx.x == 0){
    unsigned int gen = g_gen;
    if (atomicAdd(&g_count, 1u) == NB-1u){
      g_count = 0u;
      __threadfence();
      g_gen = gen + 1u;      // release
    } else {
      while (g_gen == gen) {}  // volatile spin
      __threadfence();       // acquire
    }
  }
  __syncthreads();
}

__global__ void __launch_bounds__(256, 4)
mega(const float* __restrict__ x,  const float* __restrict__ tf,
     const float* __restrict__ w1, const float* __restrict__ w2,
     const float* __restrict__ wq, const float* __restrict__ wk,
     const float* __restrict__ wv, const float* __restrict__ wo,
     float* __restrict__ out, float* __restrict__ out2){
  __shared__ float sbuf[2064];
  const int bid = blockIdx.x, tid = threadIdx.x;
  const int warp = tid>>5, lane = tid&31;

  // ================= P0: mean/max row sweep + u + q ========================
  for (int row = bid*8 + warp; row < BB*CC; row += NB*8){
    const float4* xr = (const float4*)(x + (size_t)row*HW);
    float s = 0.f, m = -CUDART_INF_F;
    #pragma unroll 2
    for (int i=lane; i<NF4; i+=32){
      float4 v = xr[i];
      s += (v.x+v.y)+(v.z+v.w);
      m = fmaxf(m, fmaxf(fmaxf(v.x,v.y), fmaxf(v.z,v.w)));
    }
    s = warp_sum(s); m = warp_max(m);
    if (lane==0){ d_avg[row] = s*(1.f/(float)HW); d_maxv[row] = m; }
  }
  if (bid >= 544 && bid < 548){
    // u[c] = sum_a wo[a]*wv[a,c]  (4 blocks x 256 c)
    int c = (bid-544)*256 + tid;
    float acc = 0.f;
    #pragma unroll 8
    for (int a=0;a<AD;a++) acc += wo[a]*wv[a*CC + c];
    d_u[c] = acc;
  } else if (bid >= 548){
    // q[b,a] = dot(tf[b,:], wq[a,:]); 256 items over 44 blocks
    for (int it = bid-548; it < 256; it += 44){
      int chunk = it & 7, b = it >> 3;
      __syncthreads();
      for (int i=tid;i<TD;i+=256) sbuf[i] = tf[b*TD+i];
      __syncthreads();
      int a0 = chunk*32 + warp*4;
      const float* q0 = wq + (a0+0)*TD;
      const float* q1 = wq + (a0+1)*TD;
      const float* q2 = wq + (a0+2)*TD;
      const float* q3 = wq + (a0+3)*TD;
      float acc0=0.f,acc1=0.f,acc2=0.f,acc3=0.f;
      #pragma unroll 4
      for (int i=lane;i<TD;i+=32){
        float t = sbuf[i];
        acc0 += q0[i]*t; acc1 += q1[i]*t; acc2 += q2[i]*t; acc3 += q3[i]*t;
      }
      acc0=warp_sum(acc0); acc1=warp_sum(acc1); acc2=warp_sum(acc2); acc3=warp_sum(acc3);
      if (lane==0){
        d_q[b*AD+a0+0]=acc0; d_q[b*AD+a0+1]=acc1;
        d_q[b*AD+a0+2]=acc2; d_q[b*AD+a0+3]=acc3;
      }
    }
  }
  gbar();

  // ================= P1: hidden MLP (256 items) || qk (128 items) ==========
  if (bid < 256){
    int b = bid>>3, rch = bid&7;
    for (int i=tid;i<CC;i+=256){ sbuf[i]=d_avg[b*CC+i]; sbuf[1024+i]=d_maxv[b*CC+i]; }
    __syncthreads();
    int r = rch*8 + warp;
    const float* wr = w1 + (size_t)r*CC;
    float a=0.f, m=0.f;
    #pragma unroll 8
    for (int i=lane;i<CC;i+=32){ float wv_=wr[i]; a+=wv_*sbuf[i]; m+=wv_*sbuf[1024+i]; }
    a=warp_sum(a); m=warp_sum(m);
    if (lane==0) d_hs[b*REDU+r] = fmaxf(a,0.f)+fmaxf(m,0.f);
  } else if (bid < 384){
    int idx = bid-256, b = idx>>2, cch = idx&3;
    if (tid < AD) sbuf[tid] = d_q[b*AD+tid];
    __syncthreads();
    int c = cch*256 + tid;
    float qk = 0.f;
    #pragma unroll 8
    for (int a=0;a<AD;a++) qk += sbuf[a]*wk[a*CC + c];
    d_qk[b*CC+c] = qk;
  }
  gbar();

  // ================= P2: ch_attn, g, h (128 items) =========================
  if (bid < 128){
    int b = bid>>2, cch = bid&3;
    if (tid < REDU) sbuf[tid] = d_hs[b*REDU+tid];
    __syncthreads();
    int c = cch*256 + tid;
    const float4* w2v = (const float4*)(w2 + (size_t)c*REDU);
    float acc = 0.f;
    #pragma unroll
    for (int r4=0;r4<REDU/4;r4++){
      float4 wv4 = w2v[r4];
      acc += wv4.x*sbuf[r4*4+0] + wv4.y*sbuf[r4*4+1]
           + wv4.z*sbuf[r4*4+2] + wv4.w*sbuf[r4*4+3];
    }
    float ch = 1.f/(1.f+__expf(-acc));
    d_chattn[b*CC+c] = ch;
    d_g[b*CC+c] = d_qk[b*CC+c] * ch * 0.0625f;   // /sqrt(256)
    d_h[b*CC+c] = d_u[c] * ch;
  }
  gbar();

  // ================= P3: dual contraction (512 items) ======================
  if (bid < NCH*BB){
    int chunk = bid & (NCH-1), b = bid >> 4;
    int c0 = chunk*NCHC;
    if (tid < NCHC){
      sbuf[tid]       = d_g[b*CC + c0 + tid];
      sbuf[NCHC+tid]  = d_h[b*CC + c0 + tid];
    }
    __syncthreads();
    if (tid < NF4){
      const float4* xb4 = (const float4*)(x + ((size_t)b*CC + c0)*HW);
      float4 aS = make_float4(0.f,0.f,0.f,0.f);
      float4 aY = make_float4(0.f,0.f,0.f,0.f);
      #pragma unroll 8
      for (int c=0;c<NCHC;c++){
        float4 v = xb4[c*NF4 + tid];
        float gc = sbuf[c], hc = sbuf[NCHC+c];
        aS.x += gc*v.x; aS.y += gc*v.y; aS.z += gc*v.z; aS.w += gc*v.w;
        aY.x += hc*v.x; aY.y += hc*v.y; aY.z += hc*v.z; aY.w += hc*v.w;
      }
      ((float4*)(d_pS + ((size_t)b*NCH + chunk)*HW))[tid] = aS;
      ((float4*)(d_pY + ((size_t)b*NCH + chunk)*HW))[tid] = aY;
    }
  }
  gbar();

  // ================= P4: softmax collapse -> s[b] (32 items) ===============
  if (bid < BB){
    int b = bid;
    const float* pS = d_pS + (size_t)b*NCH*HW;
    const float* pY = d_pY + (size_t)b*NCH*HW;
    bool has4 = tid < (HW - 768);   // tid < 16
    float sc0=0.f,sc1=0.f,sc2=0.f,sc3=0.f, y0=0.f,y1=0.f,y2=0.f,y3=0.f;
    #pragma unroll
    for (int k=0;k<NCH;k++){
      const float* ps = pS + k*HW + tid;
      const float* py = pY + k*HW + tid;
      sc0 += ps[0]; sc1 += ps[256]; sc2 += ps[512]; if (has4) sc3 += ps[768];
      y0  += py[0]; y1  += py[256]; y2  += py[512]; if (has4) y3  += py[768];
    }
    float m = fmaxf(fmaxf(sc0,sc1),sc2); if (has4) m = fmaxf(m,sc3);
    m = warp_max(m);
    if (lane==0) sbuf[warp]=m;
    __syncthreads();
    if (tid==0){ float mm=sbuf[0]; for(int i=1;i<8;i++) mm=fmaxf(mm,sbuf[i]); sbuf[32]=mm; }
    __syncthreads();
    float mm = sbuf[32];
    float e0=__expf(sc0-mm), e1=__expf(sc1-mm), e2=__expf(sc2-mm);
    float e3 = has4 ? __expf(sc3-mm) : 0.f;
    float se  = (e0+e1)+(e2+e3);
    float sey = (e0*y0+e1*y1)+(e2*y2+e3*y3);
    se = warp_sum(se); sey = warp_sum(sey);
    __syncthreads();
    if (lane==0){ sbuf[warp]=se; sbuf[8+warp]=sey; }
    __syncthreads();
    if (tid==0){
      float te=0.f, tey=0.f;
      for(int i=0;i<8;i++){ te+=sbuf[i]; tey+=sbuf[8+i]; }
      d_s[b] = 1.f/(1.f+__expf(-tey/te));
    }
  }
  gbar();

  // ================= P5: output sweep + out2 ===============================
  for (int row = bid*8 + warp; row < BB*CC; row += NB*8){
    float scale = d_chattn[row]*d_s[row>>10];
    const float4* xr = (const float4*)(x + (size_t)row*HW);
    float4* orow = (float4*)(out + (size_t)row*HW);
    #pragma unroll 2
    for (int i=lane;i<NF4;i+=32){
      float4 v = xr[i];
      v.x*=scale; v.y*=scale; v.z*=scale; v.w*=scale;
      orow[i] = v;
    }
  }
  if (out2 && bid < BB){
    float sv = d_s[bid];
    for (int n=tid;n<HW;n+=256) out2[bid*HW+n] = sv;
  }
}

extern "C" void kernel_launch(void* const* d_in, const int* in_sizes, int n_in,
                              void* d_out, int out_size){
  const float* x  = (const float*)d_in[0];
  const float* tf = (const float*)d_in[1];
  const float* w1 = (const float*)d_in[2];
  const float* w2 = (const float*)d_in[3];
  const float* wq = (const float*)d_in[4];
  const float* wk = (const float*)d_in[5];
  const float* wv = (const float*)d_in[6];
  const float* wo = (const float*)d_in[7];
  float* out = (float*)d_out;
  long long main_elems = (long long)BB*CC*HW;
  float* out2 = ((long long)out_size >= main_elems + (long long)BB*HW)
                  ? out + main_elems : nullptr;

  mega<<<NB, 256>>>(x, tf, w1, w2, wq, wk, wv, wo, out, out2);
}